// round 3
// baseline (speedup 1.0000x reference)
#include <cuda_runtime.h>
#include <cuda_bf16.h>

// Circular self-convolution: out[b,k] = sum_j x[b,j]*x[b,(k-j) mod 1024]
// B=128 rows x 3 arrays. One CTA (128 threads) per (array,row).
//
// Packed-FMA version: fma.rn.f32x2 (SASS FFMA2) doubles FMA throughput vs
// scalar FFMA (rt_SMSP=2 either way; FFMA2 does 2 FMAs/issue).
//
// Per thread: T=8 consecutive outputs as 4 packed f32x2 accumulators.
// Inner loop J=16 j-values: 64 FFMA2 per (6 window LDS.128 + 8 broadcast
// LDS.128). Window pairs (wv[m],wv[m+1]): even m free from 128-bit loads,
// odd m rebuilt via register MOVs (alu pipe). Broadcast replicated pairs
// (x_j,x_j) come from a duplicated smem row XB[2u]=XB[2u+1]=x[u].

#define N_CONV 1024
#define THREADS 128

typedef unsigned long long u64t;

__device__ __forceinline__ u64t pack2(float lo, float hi) {
    u64t r;
    asm("mov.b64 %0, {%1, %2};" : "=l"(r) : "f"(lo), "f"(hi));
    return r;
}
__device__ __forceinline__ void unpack2(u64t v, float& lo, float& hi) {
    asm("mov.b64 {%0, %1}, %2;" : "=f"(lo), "=f"(hi) : "l"(v));
}
__device__ __forceinline__ u64t ffma2(u64t a, u64t b, u64t c) {
    u64t d;
    asm("fma.rn.f32x2 %0, %1, %2, %3;" : "=l"(d) : "l"(a), "l"(b), "l"(c));
    return d;
}

__global__ __launch_bounds__(THREADS, 4)
void mcf_conv_kernel(const float* __restrict__ x1,
                     const float* __restrict__ x2,
                     const float* __restrict__ x3,
                     float* __restrict__ out)
{
    // E[v] = x[(v - 3) mod 1024], v in [0, 2052): extended circular window.
    // wv[m] = W[k0 - j - 15 + m] = E[k0 - j + 1012 + m]  (base 16B-aligned).
    __shared__ __align__(16) float E[2056];
    // XB: duplicated row, XB[2u] = XB[2u+1] = x[u]  (replicated-pair source).
    __shared__ __align__(16) float XB[2048];

    const int bx  = blockIdx.x;
    const int arr = bx >> 7;
    const int row = bx & 127;

    const float* x  = (arr == 0) ? x1 : ((arr == 1) ? x2 : x3);
    const float* xr = x + (size_t)row * N_CONV;

    const int tid = threadIdx.x;

    // Build E (scalar, coalesced; one-time cost).
    #pragma unroll
    for (int v = tid; v < 2052; v += THREADS)
        E[v] = xr[(v + 1021) & (N_CONV - 1)];
    // Build XB.
    #pragma unroll
    for (int u = tid; u < N_CONV; u += THREADS) {
        float xv = xr[u];
        XB[2 * u]     = xv;
        XB[2 * u + 1] = xv;
    }
    __syncthreads();

    const int k0 = tid * 8;            // 8 consecutive outputs per thread

    u64t acc[4];
    #pragma unroll
    for (int tp = 0; tp < 4; ++tp) acc[tp] = 0ull;

    // it-loop: j = 16*it. Window base moves down 16 floats (4 u64t2) per it;
    // broadcast base moves up 8 u64t2 per it.
    const ulonglong2* wp = (const ulonglong2*)&E[k0 + 1012];   // it = 0
    const ulonglong2* bp = (const ulonglong2*)XB;

    #pragma unroll 2
    for (int it = 0; it < N_CONV / 16; ++it) {
        // Window: wv[0..23] as 12 even pairs pe[i] = (wv[2i], wv[2i+1]).
        u64t pe[12];
        #pragma unroll
        for (int i = 0; i < 6; ++i) {
            ulonglong2 q = wp[i];
            pe[2 * i]     = q.x;
            pe[2 * i + 1] = q.y;
        }
        // Scalar view + odd pairs po[i] = (wv[2i+1], wv[2i+2]).
        float wv[24];
        #pragma unroll
        for (int i = 0; i < 12; ++i) unpack2(pe[i], wv[2 * i], wv[2 * i + 1]);
        u64t po[11];
        #pragma unroll
        for (int i = 0; i < 11; ++i) po[i] = pack2(wv[2 * i + 1], wv[2 * i + 2]);

        // Broadcast: 16 replicated pairs xb[s] = (x[j+s], x[j+s]).
        u64t xb[16];
        #pragma unroll
        for (int h = 0; h < 8; ++h) {
            ulonglong2 q = bp[h];
            xb[2 * h]     = q.x;
            xb[2 * h + 1] = q.y;
        }

        // acc2[tp] lanes (t=2tp, t=2tp+1):
        //   lane += x[j+jj] * wv[15 + t - jj]  -> pair (wv[m], wv[m+1]),
        //   m = 15 + 2*tp - jj.
        #pragma unroll
        for (int jj = 0; jj < 16; ++jj) {
            #pragma unroll
            for (int tp = 0; tp < 4; ++tp) {
                const int m = 15 + 2 * tp - jj;
                u64t wpair = (m & 1) ? po[m >> 1] : pe[m >> 1];
                acc[tp] = ffma2(xb[jj], wpair, acc[tp]);
            }
        }

        wp -= 4;   // -16 floats
        bp += 8;   // +16 doubles
    }

    // Unpack and store.
    float a[8];
    #pragma unroll
    for (int tp = 0; tp < 4; ++tp) unpack2(acc[tp], a[2 * tp], a[2 * tp + 1]);

    float* orow = out + (size_t)arr * 128 * N_CONV + (size_t)row * N_CONV;
    ((float4*)&orow[k0])[0] = make_float4(a[0], a[1], a[2], a[3]);
    ((float4*)&orow[k0])[1] = make_float4(a[4], a[5], a[6], a[7]);
}

extern "C" void kernel_launch(void* const* d_in, const int* in_sizes, int n_in,
                              void* d_out, int out_size)
{
    const float* x1 = (const float*)d_in[0];
    const float* x2 = (const float*)d_in[1];
    const float* x3 = (const float*)d_in[2];
    float* out = (float*)d_out;

    mcf_conv_kernel<<<384, THREADS>>>(x1, x2, x3, out);
}

// round 4
// speedup vs baseline: 1.1753x; 1.1753x over previous
#include <cuda_runtime.h>
#include <cuda_bf16.h>

// Circular self-convolution: out[b,k] = sum_j x[b,j]*x[b,(k-j) mod 1024]
// B=128 rows x 3 arrays. One CTA (128 threads) per (array,row).
//
// Packed-FMA (fma.rn.f32x2) with j-pairing: each FFMA2 lane-pair accumulates
// two consecutive j-terms of the SAME output:
//   lanes = (x[j], x[j+1]) * (x[k-j], x[k-j-1])
// The reversed pair (x[k-j], x[k-j-1]) is ascending-contiguous in a REVERSED
// smem copy R[u] = x[(C-u) mod N], so both FFMA2 operands are natural aligned
// 64-bit halves of LDS.128 results -> zero register marshaling (R3's failure).
//
// Each thread computes 8 outputs strided by 2 (threads 0-63 even outputs via
// RE, 64-127 odd outputs via RO = RE shifted one float), so every window pair
// lands on a compile-time u64 register index.
//
// Reversed arrays are PADDED 16->20 floats per block: lane address stride
// becomes 20 floats (80B), giving a provably uniform 4 words/bank smem access
// (vs 16-way conflict at the natural 64B stride).
//
// Rolling window: consecutive iterations overlap 16 floats, so only 4 new
// window LDS.128 per iteration -> FMA-bound, not crossbar-bound.

#define N_CONV 1024
#define THREADS 128

typedef unsigned long long u64t;

__device__ __forceinline__ u64t ffma2(u64t a, u64t b, u64t c) {
    u64t d;
    asm("fma.rn.f32x2 %0, %1, %2, %3;" : "=l"(d) : "l"(a), "l"(b), "l"(c));
    return d;
}
__device__ __forceinline__ void unpack2(u64t v, float& lo, float& hi) {
    asm("mov.b64 {%0, %1}, %2;" : "=f"(lo), "=f"(hi) : "l"(v));
}

// Padded layout: 16 logical floats per 20-float physical block.
__device__ __forceinline__ int padidx(int u) { return (u >> 4) * 20 + (u & 15); }

// Load 4 float4 (16 floats) as 8 u64 pairs.
__device__ __forceinline__ void load8u64(u64t* w, const float* p) {
    const ulonglong2* q = (const ulonglong2*)p;
    #pragma unroll
    for (int i = 0; i < 4; ++i) {
        ulonglong2 v = q[i];
        w[2 * i]     = v.x;
        w[2 * i + 1] = v.y;
    }
}

__global__ __launch_bounds__(THREADS, 4)
void mcf_conv_kernel(const float* __restrict__ x1,
                     const float* __restrict__ x2,
                     const float* __restrict__ x3,
                     float* __restrict__ out)
{
    // RE[u] = x[(1022-u) mod 1024], RO[u] = x[(1023-u) mod 1024]; u in [0,2064)
    // stored padded: 129 blocks * 20 floats = 2580.
    __shared__ __align__(16) float RE[2580];
    __shared__ __align__(16) float RO[2580];
    __shared__ __align__(16) float X[N_CONV];

    const int bx  = blockIdx.x;
    const int arr = bx >> 7;
    const int row = bx & 127;

    const float* x  = (arr == 0) ? x1 : ((arr == 1) ? x2 : x3);
    const float* xr = x + (size_t)row * N_CONV;

    const int tid = threadIdx.x;

    for (int u = tid; u < 2064; u += THREADS) {
        const int p = padidx(u);
        RE[p] = xr[(3070 - u) & (N_CONV - 1)];   // (1022-u) mod 1024
        RO[p] = xr[(3071 - u) & (N_CONV - 1)];   // (1023-u) mod 1024
    }
    for (int u = tid; u < N_CONV; u += THREADS)
        X[u] = xr[u];
    __syncthreads();

    const int par = tid >> 6;          // 0: even outputs, 1: odd outputs
    const int m   = tid & 63;
    const int k0e = m << 4;            // even base; outputs k0e+par+2t, t=0..7
    const float* Rbase = par ? RO : RE;

    // Window block index for it=0: logical B = 1008 - k0e -> block 63 - m.
    // Physical block pitch = 20 floats; advance 1 block (16 logical) per iter.
    const float* wp = Rbase + (63 - m) * 20;

    u64t acc[8];
    #pragma unroll
    for (int t = 0; t < 8; ++t) acc[t] = 0ull;

    // Rolling window registers: wlo = floats B..B+15, whi = B+16..B+31.
    u64t wlo[8], whi[8];
    load8u64(wlo, wp); wp += 20;
    load8u64(whi, wp); wp += 20;

    const float* bp = X;

    #pragma unroll 2
    for (int it = 0; it < N_CONV / 16; ++it) {
        // Broadcast pairs xp[q] = (x[j0+2q], x[j0+2q+1]), j0 = 16*it.
        u64t xp[8];
        load8u64(xp, bp);
        bp += 16;

        // acc[t] lanes += (x[j], x[j+1]) * (x[k_t-j], x[k_t-j-1]);
        // window u64 index = 7 - t + q  (0..14), all compile-time.
        #pragma unroll
        for (int q = 0; q < 8; ++q) {
            #pragma unroll
            for (int t = 0; t < 8; ++t) {
                const int i = 7 - t + q;
                const u64t w = (i < 8) ? wlo[i] : whi[i - 8];
                acc[t] = ffma2(xp[q], w, acc[t]);
            }
        }

        // Roll window down 16 logical floats; prefetch next block.
        #pragma unroll
        for (int i = 0; i < 8; ++i) wlo[i] = whi[i];
        load8u64(whi, wp);
        wp += 20;
    }

    // Horizontal add of the two j-parity lanes; scatter-store (stride 2).
    float* orow = out + (size_t)arr * 128 * N_CONV + (size_t)row * N_CONV;
    #pragma unroll
    for (int t = 0; t < 8; ++t) {
        float lo, hi;
        unpack2(acc[t], lo, hi);
        orow[k0e + par + 2 * t] = lo + hi;
    }
}

extern "C" void kernel_launch(void* const* d_in, const int* in_sizes, int n_in,
                              void* d_out, int out_size)
{
    const float* x1 = (const float*)d_in[0];
    const float* x2 = (const float*)d_in[1];
    const float* x3 = (const float*)d_in[2];
    float* out = (float*)d_out;

    mcf_conv_kernel<<<384, THREADS>>>(x1, x2, x3, out);
}